// round 8
// baseline (speedup 1.0000x reference)
#include <cuda_runtime.h>
#include <cuda_bf16.h>
#include <math.h>

// ---------------------------------------------------------------------------
// ann2_snn1 — bit-faithful emulation of the JAX/XLA-CPU reference (verified
// rel_err == 0.0). Numerics contract (must not change):
//  * every dot product: ONE f32 accumulator, strictly ascending k, IEEE RN FMA
//    (zero-padded k-tails are exact). fma.rn.f32x2 = two INDEPENDENT IEEE f32
//    FMAs in one issue slot -> contract preserved per lane of the pair.
//  * elementwise ops: separate f32 rounds in reference order
//  * logistic = 0.5 + 0.5*tanh(0.5x) with XLA's rational tanh
// ---------------------------------------------------------------------------

#define BATCH 1024
#define HID   500
#define NIN   784
#define NOUT  10
#define TLEN  100

__device__ float g_h[BATCH * HID];
__device__ float g_drive[BATCH * HID];

#define A1F ((float)1.1466802242428472)    // exp(-1/4)+exp(-1)
#define A2F ((float)-0.28650479686019009)  // -exp(-1/4)*exp(-1)
#define SGF ((float)0.77880078307140487)   // exp(-1/4)

typedef unsigned long long ull;

// ---- f32x2 packed helpers (each lane = independent IEEE f32 op) ----
__device__ __forceinline__ void ffma2(ull& d, ull a, ull b)
{
    asm("fma.rn.f32x2 %0, %1, %2, %0;" : "+l"(d) : "l"(a), "l"(b));
}
__device__ __forceinline__ ull splat2(float x)
{
    ull r;
    unsigned int u = __float_as_uint(x);
    asm("mov.b64 %0, {%1, %2};" : "=l"(r) : "r"(u), "r"(u));
    return r;
}
__device__ __forceinline__ void unpack2(ull v, float& lo, float& hi)
{
    unsigned int a, b;
    asm("mov.b64 {%0, %1}, %2;" : "=r"(a), "=r"(b) : "l"(v));
    lo = __uint_as_float(a);
    hi = __uint_as_float(b);
}

__device__ __forceinline__ float xla_tanh_f32(float x)
{
    const float kMax = 7.90531110763549805f;
    float xc = fminf(fmaxf(x, -kMax), kMax);
    float x2 = __fmul_rn(xc, xc);
    float p = -2.76076847742355e-16f;
    p = __fadd_rn(__fmul_rn(p, x2), 2.00018790482477e-13f);
    p = __fadd_rn(__fmul_rn(p, x2), -8.60467152213735e-11f);
    p = __fadd_rn(__fmul_rn(p, x2), 5.12229709037114e-08f);
    p = __fadd_rn(__fmul_rn(p, x2), 1.48572235717979e-05f);
    p = __fadd_rn(__fmul_rn(p, x2), 6.37261928875436e-04f);
    p = __fadd_rn(__fmul_rn(p, x2), 4.89352455891786e-03f);
    float num = __fmul_rn(xc, p);
    float q = 1.19825839466702e-06f;
    q = __fadd_rn(__fmul_rn(q, x2), 1.18534705686654e-04f);
    q = __fadd_rn(__fmul_rn(q, x2), 2.26843463243900e-03f);
    q = __fadd_rn(__fmul_rn(q, x2), 4.89352518554385e-03f);
    float r = __fdiv_rn(num, q);
    return (fabsf(x) < 0.0004f) ? x : r;
}

__device__ __forceinline__ float xla_sigmoid(float x)
{
    float t = xla_tanh_f32(__fmul_rn(0.5f, x));
    return __fadd_rn(0.5f, __fmul_rn(0.5f, t));
}

// ---------------------------------------------------------------------------
// SGEMM with FFMA2: C[M,N] = act(A[M,K] @ W[N,K]^T + bias[N])
// BM=32, BN=32, BK=16, 128 threads, 2x4 micro-tile as 4 f32x2 accumulators
// (pairs across adjacent n). A staged DUPLICATED so LDS.64 yields (a,a)
// splats; W float4 rows read as ulonglong2 = (w0,w1),(w2,w3) pairs.
// Double-buffered via register prefetch. Grid 512 -> ~3.5 blocks/SM.
// ---------------------------------------------------------------------------
#define BM 32
#define BN 32
#define BK 16
#define AS_LD 66    // 2*32 dup + 2 pad (row stride 264B, 8B-aligned)
#define WS_LD 36    // 32 + 4 pad (row stride 144B, 16B-aligned)

template<int ACT>
__global__ __launch_bounds__(128)
void gemm_bias_act(const float* __restrict__ A, const float* __restrict__ W,
                   const float* __restrict__ bias, float* __restrict__ C,
                   int M, int N, int K)
{
    __shared__ float As2[2][BK][AS_LD];
    __shared__ float Ws[2][BK][WS_LD];

    const int tid = threadIdx.x;
    const int tx  = tid & 7;            // n-quad: cols tx*4..+3
    const int ty  = tid >> 3;           // m-pair: rows ty*2, ty*2+1
    const int bm  = blockIdx.y * BM;
    const int bn  = blockIdx.x * BN;

    const int lrow = tid >> 2;          // 0..31
    const int lc4  = tid & 3;           // 0..3 -> k offset lc4*4

    const int T = (K + BK - 1) / BK;

    ull acc00 = 0, acc01 = 0, acc10 = 0, acc11 = 0;
    float4 pa, pw;

    auto loadA = [&](int kb) {
        int k = kb + lc4 * 4;
        const float* ap = A + (size_t)(bm + lrow) * K;
        float4 v;
        if (k + 3 < K) {
            v = *(const float4*)(ap + k);
        } else {
            v.x = (k + 0 < K) ? ap[k + 0] : 0.f;
            v.y = (k + 1 < K) ? ap[k + 1] : 0.f;
            v.z = (k + 2 < K) ? ap[k + 2] : 0.f;
            v.w = (k + 3 < K) ? ap[k + 3] : 0.f;
        }
        pa = v;
    };
    auto loadW = [&](int kb) {
        int wr = bn + lrow;
        int k  = kb + lc4 * 4;
        float4 v = make_float4(0.f, 0.f, 0.f, 0.f);
        if (wr < N) {
            const float* wp = W + (size_t)wr * K;
            if (k + 3 < K) {
                v = *(const float4*)(wp + k);
            } else {
                v.x = (k + 0 < K) ? wp[k + 0] : 0.f;
                v.y = (k + 1 < K) ? wp[k + 1] : 0.f;
                v.z = (k + 2 < K) ? wp[k + 2] : 0.f;
                v.w = (k + 3 < K) ? wp[k + 3] : 0.f;
            }
        }
        pw = v;
    };
    auto stage = [&](int buf) {
        int ka = lc4 * 4;
        // duplicated A: (v,v) at [2*lrow, 2*lrow+1] via STS.64
        *(float2*)&As2[buf][ka + 0][2 * lrow] = make_float2(pa.x, pa.x);
        *(float2*)&As2[buf][ka + 1][2 * lrow] = make_float2(pa.y, pa.y);
        *(float2*)&As2[buf][ka + 2][2 * lrow] = make_float2(pa.z, pa.z);
        *(float2*)&As2[buf][ka + 3][2 * lrow] = make_float2(pa.w, pa.w);
        Ws[buf][ka + 0][lrow] = pw.x;
        Ws[buf][ka + 1][lrow] = pw.y;
        Ws[buf][ka + 2][lrow] = pw.z;
        Ws[buf][ka + 3][lrow] = pw.w;
    };

    loadA(0);
    loadW(0);
    stage(0);
    __syncthreads();

    for (int it = 0; it < T; it++) {
        const int cur = it & 1;
        if (it + 1 < T) {
            loadA((it + 1) * BK);
            loadW((it + 1) * BK);
        }
        #pragma unroll
        for (int k = 0; k < BK; k++) {
            ull a0 = *(const ull*)&As2[cur][k][ty * 4];       // (a_row0, a_row0)
            ull a1 = *(const ull*)&As2[cur][k][ty * 4 + 2];   // (a_row1, a_row1)
            ulonglong2 wv = *(const ulonglong2*)&Ws[cur][k][tx * 4]; // (w0,w1),(w2,w3)
            ffma2(acc00, a0, wv.x);
            ffma2(acc01, a0, wv.y);
            ffma2(acc10, a1, wv.x);
            ffma2(acc11, a1, wv.y);
        }
        if (it + 1 < T) stage(cur ^ 1);
        __syncthreads();
    }

    // epilogue: unpack, bias (separate f32 add), activation, float4 stores
    const int n0 = bn + tx * 4;
    if (n0 < N) {
        float bv0 = bias[n0 + 0], bv1 = bias[n0 + 1];
        float bv2 = bias[n0 + 2], bv3 = bias[n0 + 3];
        float r00, r01, r02, r03, r10, r11, r12, r13;
        unpack2(acc00, r00, r01); unpack2(acc01, r02, r03);
        unpack2(acc10, r10, r11); unpack2(acc11, r12, r13);
        float o[2][4] = {{__fadd_rn(r00, bv0), __fadd_rn(r01, bv1),
                          __fadd_rn(r02, bv2), __fadd_rn(r03, bv3)},
                         {__fadd_rn(r10, bv0), __fadd_rn(r11, bv1),
                          __fadd_rn(r12, bv2), __fadd_rn(r13, bv3)}};
        #pragma unroll
        for (int i = 0; i < 2; i++) {
            int m = bm + ty * 2 + i;
            float x0 = o[i][0], x1 = o[i][1], x2 = o[i][2], x3 = o[i][3];
            if (ACT == 0) {
                x0 = fmaxf(x0, 0.f); x1 = fmaxf(x1, 0.f);
                x2 = fmaxf(x2, 0.f); x3 = fmaxf(x3, 0.f);
            } else {
                x0 = xla_sigmoid(x0); x1 = xla_sigmoid(x1);
                x2 = xla_sigmoid(x2); x3 = xla_sigmoid(x3);
            }
            *(float4*)&C[(size_t)m * N + n0] = make_float4(x0, x1, x2, x3);
        }
    }
}

// ---------------------------------------------------------------------------
// Scan kernel: one block (256 threads) per batch element.
//  phase 1: 250 threads x 2 cols iterate psp (reference op order) -> smem.
//  phase 2: thread = t (warps 0-3), ALL 10 j as 5 f32x2 chains. Weights
//           pre-interleaved as pairs swp[p][k] = (w3[2p][k], w3[2p+1][k]);
//           pair loads are warp-uniform (broadcast). Per 4-k step:
//           1 psp LDS.128 + 4 splat packs + 10 pair LDS.128 + 20 FFMA2.
//           Each f32x2 lane is one strict ascending-k IEEE FMA chain.
//  phase 3: 10 threads run the LIF recurrence (per-op f32 rounds).
// ---------------------------------------------------------------------------
__global__ __launch_bounds__(256)
void scan_kernel(const float* __restrict__ w3g, const float* __restrict__ b3,
                 float* __restrict__ out)
{
    extern __shared__ float sm[];
    float*  sp  = sm;                      // [TLEN][HID]   psp    (200,000 B)
    float2* swp = (float2*)(sm + TLEN * HID);  // [5][HID] pairs (20,000 B)
    float*  sc  = sm + TLEN * HID + 5 * HID * 2;  // [TLEN][NOUT]  (4,000 B)

    const int b   = blockIdx.x;
    const int tid = threadIdx.x;

    // build interleaved weight pairs: swp[p*HID + k] = (w3[2p][k], w3[2p+1][k])
    for (int i = tid; i < 5 * HID; i += 256) {
        int p = i / HID, k = i - p * HID;
        swp[i] = make_float2(w3g[(2 * p) * HID + k], w3g[(2 * p + 1) * HID + k]);
    }

    // phase 1: psp recurrence, 2 columns per thread
    if (tid < 250) {
        const int k0 = tid, k1 = tid + 250;
        float d0 = g_drive[(size_t)b * HID + k0];
        float d1 = g_drive[(size_t)b * HID + k1];
        float p1a = 0.f, p2a = 0.f, p1b = 0.f, p2b = 0.f;
        #pragma unroll 4
        for (int t = 0; t < TLEN; t++) {
            float pa = __fadd_rn(__fadd_rn(__fmul_rn(A1F, p1a),
                                           __fmul_rn(A2F, p2a)), d0);
            float pb = __fadd_rn(__fadd_rn(__fmul_rn(A1F, p1b),
                                           __fmul_rn(A2F, p2b)), d1);
            sp[t * HID + k0] = pa;
            sp[t * HID + k1] = pb;
            p2a = p1a; p1a = pa;
            p2b = p1b; p1b = pb;
        }
    }
    __syncthreads();

    // phase 2: thread = t, 5 f32x2 chains covering all 10 j
    if (tid < TLEN) {
        const int t = tid;
        const float* pr = sp + t * HID;
        ull acc[5] = {0, 0, 0, 0, 0};
        #pragma unroll 5
        for (int k = 0; k < HID; k += 4) {
            float4 pv = *(const float4*)(pr + k);
            ull s0 = splat2(pv.x);
            ull s1 = splat2(pv.y);
            ull s2 = splat2(pv.z);
            ull s3 = splat2(pv.w);
            #pragma unroll
            for (int p = 0; p < 5; p++) {
                const float2* pb2 = swp + p * HID + k;
                ulonglong2 w01 = *(const ulonglong2*)(pb2);      // pairs k, k+1
                ulonglong2 w23 = *(const ulonglong2*)(pb2 + 2);  // pairs k+2, k+3
                ffma2(acc[p], s0, w01.x);
                ffma2(acc[p], s1, w01.y);
                ffma2(acc[p], s2, w23.x);
                ffma2(acc[p], s3, w23.y);
            }
        }
        float* scr = sc + t * NOUT;
        #pragma unroll
        for (int p = 0; p < 5; p++) {
            float lo, hi;
            unpack2(acc[p], lo, hi);
            scr[2 * p]     = lo;
            scr[2 * p + 1] = hi;
        }
    }
    __syncthreads();

    // phase 3: LIF recurrence (exact reference op order); spikes -> sp region
    if (tid < NOUT) {
        float bb = b3[tid];
        float v = 0.f, s = 0.f;
        float* spk = sp + tid * TLEN;
        for (int t = 0; t < TLEN; t++) {
            float cur = __fadd_rn(sc[t * NOUT + tid], bb);
            float t1  = __fmul_rn(SGF, v);
            float t2  = __fmul_rn(t1, __fsub_rn(1.f, s));
            float vn  = __fadd_rn(t2, cur);
            s = (vn >= 1.f) ? 1.f : 0.f;
            v = vn;
            spk[t] = s;
        }
    }
    __syncthreads();

    float* ob = out + (size_t)b * (NOUT * TLEN);
    for (int i = tid; i < NOUT * TLEN; i += 256) ob[i] = sp[i];
}

#define SCAN_SMEM ((TLEN * HID + 2 * 5 * HID + TLEN * NOUT) * (int)sizeof(float))

extern "C" void kernel_launch(void* const* d_in, const int* in_sizes, int n_in,
                              void* d_out, int out_size)
{
    const float* inputs = (const float*)d_in[0];  // [1024, 784]
    const float* w1     = (const float*)d_in[1];  // [500, 784]
    const float* b1     = (const float*)d_in[2];  // [500]
    const float* w2     = (const float*)d_in[3];  // [500, 500]
    const float* b2     = (const float*)d_in[4];  // [500]
    const float* w3     = (const float*)d_in[5];  // [10, 500]
    const float* b3     = (const float*)d_in[6];  // [10]
    float* out          = (float*)d_out;          // [1024, 10, 100]

    float* h_buf;
    float* drive_buf;
    cudaGetSymbolAddress((void**)&h_buf, g_h);
    cudaGetSymbolAddress((void**)&drive_buf, g_drive);

    cudaFuncSetAttribute(scan_kernel,
                         cudaFuncAttributeMaxDynamicSharedMemorySize, SCAN_SMEM);

    dim3 blk(128);
    dim3 grd((HID + BN - 1) / BN, BATCH / BM);   // 16 x 32 = 512 blocks
    gemm_bias_act<0><<<grd, blk>>>(inputs, w1, b1, h_buf, BATCH, HID, NIN);
    gemm_bias_act<1><<<grd, blk>>>(h_buf, w2, b2, drive_buf, BATCH, HID, HID);
    scan_kernel<<<BATCH, 256, SCAN_SMEM>>>(w3, b3, out);
}